// round 13
// baseline (speedup 1.0000x reference)
#include <cuda_runtime.h>
#include <cuda_bf16.h>
#include <cstdint>

// ---------------------------------------------------------------------------
// APPNP dense surrogate, N=8192, F=MLP=512, C=256, 10 power iters, alpha=0.1.
// sm_103 (non-'a'): legacy mma.sync bf16 only.
// v5 GEMM: BM=64 BN=128 BK=64, 4-stage cp.async, ldmatrix fragments with
// EXPLICIT kk-level double buffering (volatile-asm order = issue order:
// LDSM(kk+1) is issued before MMA(kk) so shared-load latency hides under the
// previous MMA batch), __launch_bounds__(256,2) -> 2 CTAs/SM.
// Transposed-activation layout: B operand always K-major [N,K].
// ---------------------------------------------------------------------------

#define NN   8192
#define FD   512
#define CD   256
#define ALPHA 0.1f

#define BMr 64
#define BNr 128
#define BKr 64
#define STRB 144                         // smem row stride bytes (72 bf16)
#define A_TILE_B (BMr * STRB)            // 9216
#define B_TILE_B (BNr * STRB)            // 18432
#define STG_B    (A_TILE_B + B_TILE_B)   // 27648
#define NSTG 4
#define SMEM_TOT (NSTG * STG_B)          // 110592 -> 2 CTAs/SM

// ---- scratch ---------------------------------------------------------------
__device__ __nv_bfloat16 g_Abf[(size_t)NN * NN];     // 128 MB
__device__ __nv_bfloat16 g_Fbf[(size_t)NN * FD];
__device__ __nv_bfloat16 g_W0t[FD * FD];
__device__ __nv_bfloat16 g_W1t[FD * FD];
__device__ __nv_bfloat16 g_Wot[FD * CD];
__device__ __nv_bfloat16 g_Yt[(size_t)FD * NN];
__device__ __nv_bfloat16 g_X[(size_t)NN * FD];
__device__ __nv_bfloat16 g_Z0t[(size_t)CD * NN];
__device__ __nv_bfloat16 g_Za[(size_t)CD * NN];
__device__ __nv_bfloat16 g_Zb[(size_t)CD * NN];

__device__ __forceinline__ uint32_t sptr(const void* p) {
    return (uint32_t)__cvta_generic_to_shared(p);
}
__device__ __forceinline__ void ldsm4(uint32_t a, uint32_t* r) {
    asm volatile("ldmatrix.sync.aligned.m8n8.x4.shared.b16 {%0,%1,%2,%3}, [%4];"
                 : "=r"(r[0]), "=r"(r[1]), "=r"(r[2]), "=r"(r[3]) : "r"(a));
}

// ---- converts --------------------------------------------------------------
__global__ void f32_to_bf16_kernel(const float* __restrict__ src,
                                   __nv_bfloat16* __restrict__ dst, long n8) {
    long t = (long)blockIdx.x * blockDim.x + threadIdx.x;
    if (t >= n8) return;
    long i = t * 8;
    float4 a = *(const float4*)(src + i);
    float4 b = *(const float4*)(src + i + 4);
    union { int4 v; __nv_bfloat16 h[8]; } u;
    u.h[0] = __float2bfloat16(a.x); u.h[1] = __float2bfloat16(a.y);
    u.h[2] = __float2bfloat16(a.z); u.h[3] = __float2bfloat16(a.w);
    u.h[4] = __float2bfloat16(b.x); u.h[5] = __float2bfloat16(b.y);
    u.h[6] = __float2bfloat16(b.z); u.h[7] = __float2bfloat16(b.w);
    *(int4*)(dst + i) = u.v;
}

__global__ void wcvt_T_kernel(const float* __restrict__ W0,
                              const float* __restrict__ W1,
                              const float* __restrict__ Wo,
                              __nv_bfloat16* __restrict__ W0t,
                              __nv_bfloat16* __restrict__ W1t,
                              __nv_bfloat16* __restrict__ Wot) {
    __shared__ float t[32][33];
    const float* src; __nv_bfloat16* dst; int C;
    if (blockIdx.z == 0)      { src = W0; dst = W0t; C = FD; }
    else if (blockIdx.z == 1) { src = W1; dst = W1t; C = FD; }
    else                      { src = Wo; dst = Wot; C = CD; }
    int c0 = blockIdx.x * 32, r0 = blockIdx.y * 32;
    if (c0 >= C) return;
    int tx = threadIdx.x, ty = threadIdx.y;   // (32, 8)
#pragma unroll
    for (int j = 0; j < 32; j += 8)
        t[ty + j][tx] = src[(size_t)(r0 + ty + j) * C + c0 + tx];
    __syncthreads();
#pragma unroll
    for (int j = 0; j < 32; j += 8)
        dst[(size_t)(c0 + ty + j) * FD + r0 + tx] = __float2bfloat16(t[tx][ty + j]);
}

// ---- v5 bf16 GEMM: C[M,N] = epi(Aop[M,K] @ B), B given as Bt[N,K] ---------
// MODE 0: acc + bias[row]   MODE 1: relu(acc)   MODE 2: 0.9*acc + 0.1*Z0[r,c]
// 8 warps, warp tile 32x32 (mi=2 m16 tiles, nj=4 n8 tiles).
template <int MODE>
__global__ void __launch_bounds__(256, 2)
gemm_v5(const __nv_bfloat16* __restrict__ Aop,
        const __nv_bfloat16* __restrict__ Btp,
        __nv_bfloat16* __restrict__ Cmat,
        int M, int N, int K,
        const float* __restrict__ bias,
        const __nv_bfloat16* __restrict__ Z0) {
    extern __shared__ char sm[];
    const uint32_t base = sptr(sm);

    const int tid  = threadIdx.x;
    const int lane = tid & 31;
    const int warp = tid >> 5;
    const int wm = (warp & 1) * 32;
    const int wn = (warp >> 1) * 32;
    const int bm0 = blockIdx.y * BMr;
    const int bn0 = blockIdx.x * BNr;
    const int nIter = K / BKr;

    auto load_stage = [&](int st, int kiter) {
        const int k0 = kiter * BKr;
        const uint32_t sa = base + st * STG_B;
        const uint32_t sb = sa + A_TILE_B;
#pragma unroll
        for (int i = 0; i < 2; i++) {         // A: 64 rows x 8 16B-chunks
            int id = tid + i * 256, row = id >> 3, c = id & 7;
            const void* g = Aop + (size_t)(bm0 + row) * K + k0 + c * 8;
            asm volatile("cp.async.cg.shared.global [%0], [%1], 16;\n"
                         :: "r"(sa + row * STRB + c * 16), "l"(g));
        }
#pragma unroll
        for (int i = 0; i < 4; i++) {         // B: 128 rows x 8 chunks
            int id = tid + i * 256, row = id >> 3, c = id & 7;
            const void* g = Btp + (size_t)(bn0 + row) * K + k0 + c * 8;
            asm volatile("cp.async.cg.shared.global [%0], [%1], 16;\n"
                         :: "r"(sb + row * STRB + c * 16), "l"(g));
        }
        asm volatile("cp.async.commit_group;\n");
    };

    // ldmatrix lane addressing: tile = lane>>3 -> (row +8 if bit0, col +8 if bit1)
    const int lrow   = (lane & 7) + ((lane >> 3) & 1) * 8;
    const int lcol16 = (lane >> 4) * 16;             // byte offset (+8 elems)
    const uint32_t aoff = (uint32_t)(wm + lrow) * STRB + lcol16;
    const uint32_t boff = (uint32_t)(wn + lrow) * STRB + lcol16;

    float acc[2][4][4];
#pragma unroll
    for (int i = 0; i < 2; i++)
#pragma unroll
        for (int j = 0; j < 4; j++)
#pragma unroll
            for (int k = 0; k < 4; k++) acc[i][j][k] = 0.f;

    // double-buffered fragments (kk granularity)
    uint32_t af[2][2][4], bf[2][2][4];

    // prologue: fill NSTG-1 = 3 stages
    load_stage(0, 0);
    load_stage(1, 1);
    load_stage(2, 2);

    for (int it = 0; it < nIter; it++) {
        asm volatile("cp.async.wait_group %0;\n" :: "n"(NSTG - 2));
        __syncthreads();

        const uint32_t sa = base + (it % NSTG) * STG_B;
        const uint32_t sb = sa + A_TILE_B;

        // issue kk=0 fragment loads FIRST...
#pragma unroll
        for (int mi = 0; mi < 2; mi++) ldsm4(sa + aoff + mi * 16 * STRB, af[0][mi]);
#pragma unroll
        for (int nb = 0; nb < 2; nb++) ldsm4(sb + boff + nb * 16 * STRB, bf[0][nb]);

        // ...then the next-stage cp.async (covers the LDSM latency for free)
        int nxt = it + NSTG - 1;
        if (nxt < nIter) load_stage(nxt % NSTG, nxt);
        else asm volatile("cp.async.commit_group;\n");

#pragma unroll
        for (int kk = 0; kk < 4; kk++) {              // kk16 steps, bytes = kk*32
            const int cur = kk & 1, nx = cur ^ 1;
            if (kk < 3) {                             // prefetch kk+1 frags
#pragma unroll
                for (int mi = 0; mi < 2; mi++)
                    ldsm4(sa + aoff + mi * 16 * STRB + (kk + 1) * 32, af[nx][mi]);
#pragma unroll
                for (int nb = 0; nb < 2; nb++)
                    ldsm4(sb + boff + nb * 16 * STRB + (kk + 1) * 32, bf[nx][nb]);
            }
            // bf[..][nb]: r0=b0(nj=2nb) r1=b0(nj=2nb+1) r2=b1(nj=2nb) r3=b1(nj=2nb+1)
#pragma unroll
            for (int mi = 0; mi < 2; mi++)
#pragma unroll
                for (int nj = 0; nj < 4; nj++) {
                    uint32_t b0 = bf[cur][nj >> 1][nj & 1];
                    uint32_t b1 = bf[cur][nj >> 1][2 + (nj & 1)];
                    asm volatile(
                        "mma.sync.aligned.m16n8k16.row.col.f32.bf16.bf16.f32 "
                        "{%0,%1,%2,%3}, {%4,%5,%6,%7}, {%8,%9}, {%0,%1,%2,%3};\n"
                        : "+f"(acc[mi][nj][0]), "+f"(acc[mi][nj][1]),
                          "+f"(acc[mi][nj][2]), "+f"(acc[mi][nj][3])
                        : "r"(af[cur][mi][0]), "r"(af[cur][mi][1]),
                          "r"(af[cur][mi][2]), "r"(af[cur][mi][3]),
                          "r"(b0), "r"(b1));
                }
        }
    }

    // --- epilogue ---
#pragma unroll
    for (int mi = 0; mi < 2; mi++) {
#pragma unroll
        for (int nj = 0; nj < 4; nj++) {
            int row0 = bm0 + wm + mi * 16 + (lane >> 2);
            int col  = bn0 + wn + nj * 8 + (lane & 3) * 2;
#pragma unroll
            for (int h = 0; h < 2; h++) {
                int row = row0 + h * 8;
                float v0 = acc[mi][nj][2 * h + 0];
                float v1 = acc[mi][nj][2 * h + 1];
                if (MODE == 0) { float b = bias[row]; v0 += b; v1 += b; }
                if (MODE == 1) { v0 = fmaxf(v0, 0.f); v1 = fmaxf(v1, 0.f); }
                if (MODE == 2) {
                    __nv_bfloat162 z = *(const __nv_bfloat162*)(Z0 + (size_t)row * N + col);
                    v0 = (1.f - ALPHA) * v0 + ALPHA * __bfloat162float(z.x);
                    v1 = (1.f - ALPHA) * v1 + ALPHA * __bfloat162float(z.y);
                }
                *(__nv_bfloat162*)(Cmat + (size_t)row * N + col) = __floats2bfloat162_rn(v0, v1);
            }
        }
    }
}

// ---- column softmax of Zt[256, 8192] -> out[8192, 256] fp32 ---------------
__global__ void softmax_T_kernel(const __nv_bfloat16* __restrict__ Zt,
                                 float* __restrict__ out) {
    __shared__ float tile[2][32][33];
    int warp = threadIdx.x >> 5, lane = threadIdx.x & 31;
    int n0 = blockIdx.x * 64 + warp * 32;
    int n = n0 + lane;

    float mx = -1e30f;
#pragma unroll 8
    for (int c = 0; c < CD; c++)
        mx = fmaxf(mx, __bfloat162float(Zt[(size_t)c * NN + n]));
    float s = 0.f;
#pragma unroll 8
    for (int c = 0; c < CD; c++)
        s += __expf(__bfloat162float(Zt[(size_t)c * NN + n]) - mx);
    float inv = 1.f / s;

    for (int c0 = 0; c0 < CD; c0 += 32) {
#pragma unroll
        for (int cc = 0; cc < 32; cc++)
            tile[warp][cc][lane] =
                __expf(__bfloat162float(Zt[(size_t)(c0 + cc) * NN + n]) - mx) * inv;
        __syncwarp();
#pragma unroll
        for (int i = 0; i < 32; i++)
            out[(size_t)(n0 + i) * CD + c0 + lane] = tile[warp][lane][i];
        __syncwarp();
    }
}

// ---------------------------------------------------------------------------
extern "C" void kernel_launch(void* const* d_in, const int* in_sizes, int n_in,
                              void* d_out, int out_size) {
    const float* features = (const float*)d_in[0];
    const float* fltr     = (const float*)d_in[1];
    const float* W0       = (const float*)d_in[2];
    const float* b0       = (const float*)d_in[3];
    const float* W1       = (const float*)d_in[4];
    const float* b1       = (const float*)d_in[5];
    const float* Wo       = (const float*)d_in[6];
    const float* bo       = (const float*)d_in[7];

    void *pA, *pF, *pW0, *pW1, *pWo, *pYt, *pX, *pZ0, *pZa, *pZb;
    cudaGetSymbolAddress(&pA,  g_Abf);
    cudaGetSymbolAddress(&pF,  g_Fbf);
    cudaGetSymbolAddress(&pW0, g_W0t);
    cudaGetSymbolAddress(&pW1, g_W1t);
    cudaGetSymbolAddress(&pWo, g_Wot);
    cudaGetSymbolAddress(&pYt, g_Yt);
    cudaGetSymbolAddress(&pX,  g_X);
    cudaGetSymbolAddress(&pZ0, g_Z0t);
    cudaGetSymbolAddress(&pZa, g_Za);
    cudaGetSymbolAddress(&pZb, g_Zb);

    __nv_bfloat16* Abf = (__nv_bfloat16*)pA;
    __nv_bfloat16* Fbf = (__nv_bfloat16*)pF;
    __nv_bfloat16* W0t = (__nv_bfloat16*)pW0;
    __nv_bfloat16* W1t = (__nv_bfloat16*)pW1;
    __nv_bfloat16* Wot = (__nv_bfloat16*)pWo;
    __nv_bfloat16* Yt  = (__nv_bfloat16*)pYt;
    __nv_bfloat16* Xb  = (__nv_bfloat16*)pX;
    __nv_bfloat16* Z0t = (__nv_bfloat16*)pZ0;
    __nv_bfloat16* Za  = (__nv_bfloat16*)pZa;
    __nv_bfloat16* Zb  = (__nv_bfloat16*)pZb;

    cudaFuncSetAttribute(gemm_v5<0>, cudaFuncAttributeMaxDynamicSharedMemorySize, SMEM_TOT);
    cudaFuncSetAttribute(gemm_v5<1>, cudaFuncAttributeMaxDynamicSharedMemorySize, SMEM_TOT);
    cudaFuncSetAttribute(gemm_v5<2>, cudaFuncAttributeMaxDynamicSharedMemorySize, SMEM_TOT);

    // 0) converts
    {
        long n8 = (long)NN * NN / 8;
        f32_to_bf16_kernel<<<(int)((n8 + 255) / 256), 256>>>(fltr, Abf, n8);
        long f8 = (long)NN * FD / 8;
        f32_to_bf16_kernel<<<(int)((f8 + 255) / 256), 256>>>(features, Fbf, f8);
        wcvt_T_kernel<<<dim3(16, 16, 3), dim3(32, 8)>>>(W0, W1, Wo, W0t, W1t, Wot);
    }

    dim3 gridYt(NN / BNr, FD / BMr);   // (64, 8)  = 512 CTAs  [512,8192]
    dim3 gridX (FD / BNr, NN / BMr);   // (4, 128) = 512 CTAs  [8192,512]
    dim3 gridZ (NN / BNr, CD / BMr);   // (64, 4)  = 256 CTAs  [256,8192]

    // 1) Yt = W0t @ Ft (+b0 row)
    gemm_v5<0><<<gridYt, 256, SMEM_TOT>>>(W0t, Fbf, Yt, FD, NN, FD, b0, nullptr);
    // 2) X = relu(A @ Y)   (Bt = Yt)
    gemm_v5<1><<<gridX, 256, SMEM_TOT>>>(Abf, Yt, Xb, NN, FD, NN, nullptr, nullptr);
    // 3) Yt = W1t @ Xt (+b1 row)
    gemm_v5<0><<<gridYt, 256, SMEM_TOT>>>(W1t, Xb, Yt, FD, NN, FD, b1, nullptr);
    // 4) X = relu(A @ Y2)
    gemm_v5<1><<<gridX, 256, SMEM_TOT>>>(Abf, Yt, Xb, NN, FD, NN, nullptr, nullptr);
    // 5) Z0t = Wot @ X2t (+bo row)
    gemm_v5<0><<<gridZ, 256, SMEM_TOT>>>(Wot, Xb, Z0t, CD, NN, FD, bo, nullptr);

    // 6) 10x: Zt = 0.9 * Zt @ At + 0.1 * Z0t   (Bt = A natural)
    __nv_bfloat16* zin = Z0t;
    __nv_bfloat16* zout = Za;
    for (int it = 0; it < 10; it++) {
        gemm_v5<2><<<gridZ, 256, SMEM_TOT>>>(zin, Abf, zout, CD, NN, NN, nullptr, Z0t);
        zin = zout;
        zout = (zin == Za) ? Zb : Za;
    }

    // 7) column softmax -> [8192, 256] fp32
    softmax_T_kernel<<<NN / 64, 64>>>(zin, (float*)d_out);
}